// round 2
// baseline (speedup 1.0000x reference)
#include <cuda_runtime.h>

#define N_NODES  20000
#define N_EDGES  320000
#define F_EDGE   32
#define D_IN     16
#define D_NN     16
#define D_GAT    64
#define HID      128
#define N_GRAPHS 64
#define NEG_SLOPE 0.2f
#define X2_ROWS  33            // 32 edge-feature rows + 1 bias row (ea == 1)
#define X2_STRIDE (X2_ROWS * D_NN)   // 528 floats per node

// ---------------- scratch (static __device__, per harness rules) ----------------
static __device__ __align__(16) float    g_X2[N_NODES * X2_STRIDE];   // 42.2 MB
static __device__ __align__(16) float    g_agg[N_NODES * D_NN];
static __device__ __align__(16) float    g_hp[N_NODES * D_GAT];
static __device__ __align__(16) float    g_gat[N_NODES * D_GAT];
static __device__ __align__(16) float    g_pooled[N_GRAPHS * D_GAT];
static __device__ float    g_scs[N_NODES];
static __device__ float    g_scd[N_NODES];
static __device__ float    g_eself[N_NODES];
static __device__ float    g_exself[N_NODES];
static __device__ float    g_mf[N_NODES];
static __device__ float    g_denom[N_NODES];
static __device__ unsigned g_menc[N_NODES];
static __device__ float    g_eedge[N_EDGES];
static __device__ float    g_exedge[N_EDGES];
static __device__ float    g_cnt[N_GRAPHS];

// ---------------- helpers ----------------
__device__ __forceinline__ unsigned fenc(float f) {
    unsigned u = __float_as_uint(f);
    return (u & 0x80000000u) ? ~u : (u | 0x80000000u);
}
__device__ __forceinline__ float fdec(unsigned k) {
    unsigned u = (k & 0x80000000u) ? (k ^ 0x80000000u) : ~k;
    return __uint_as_float(u);
}
__device__ __forceinline__ void red_add_v4(float* p, float4 v) {
    asm volatile("red.global.add.v4.f32 [%0], {%1,%2,%3,%4};"
                 :: "l"(p), "f"(v.x), "f"(v.y), "f"(v.z), "f"(v.w) : "memory");
}
__device__ __forceinline__ float lrelu(float v) { return v > 0.f ? v : NEG_SLOPE * v; }

// ---------------- K0: zero accumulators ----------------
__global__ void k_init() {
    int t = blockIdx.x * blockDim.x + threadIdx.x;
    int stride = gridDim.x * blockDim.x;
    for (int i = t; i < N_NODES * D_NN; i += stride) g_agg[i] = 0.f;
    for (int i = t; i < N_NODES; i += stride) g_menc[i] = 0u;
    for (int i = t; i < N_GRAPHS * D_GAT; i += stride) g_pooled[i] = 0.f;
    for (int i = t; i < N_GRAPHS; i += stride) g_cnt[i] = 0.f;
}

// ---------------- K1: X2[n,f,o] = sum_i x[n,i] * We[f, i*16+o]  (f==32 -> be row) ----------------
__global__ void k_x2(const float* __restrict__ x, const float* __restrict__ We,
                     const float* __restrict__ be) {
    int t = blockIdx.x * blockDim.x + threadIdx.x;
    if (t >= N_NODES * X2_ROWS) return;
    int n = t / X2_ROWS, f = t % X2_ROWS;
    float xv[D_IN];
#pragma unroll
    for (int i = 0; i < D_IN; i++) xv[i] = __ldg(&x[n * D_IN + i]);
    const float* w = (f < F_EDGE) ? (We + (size_t)f * (D_IN * D_NN)) : be;
    float* out = g_X2 + (size_t)n * X2_STRIDE + f * D_NN;
#pragma unroll
    for (int o = 0; o < D_NN; o += 4) {
        float4 acc = make_float4(0.f, 0.f, 0.f, 0.f);
#pragma unroll
        for (int i = 0; i < D_IN; i++) {
            float4 wv = *reinterpret_cast<const float4*>(&w[i * D_NN + o]);
            acc.x += xv[i] * wv.x; acc.y += xv[i] * wv.y;
            acc.z += xv[i] * wv.z; acc.w += xv[i] * wv.w;
        }
        *reinterpret_cast<float4*>(&out[o]) = acc;
    }
}

// ---------------- K2: per-edge NNConv message + scatter.  4 threads / edge ----------------
__global__ void k_nnconv(const int* __restrict__ ei, const float* __restrict__ ea) {
    int t = blockIdx.x * blockDim.x + threadIdx.x;
    if (t >= N_EDGES * 4) return;
    int e = t >> 2, og = t & 3;
    int src = ei[e];
    int dst = ei[N_EDGES + e];
    const float* base = g_X2 + (size_t)src * X2_STRIDE + og * 4;
    float4 acc = make_float4(0.f, 0.f, 0.f, 0.f);
#pragma unroll 8
    for (int f = 0; f < F_EDGE; f++) {
        float a = __ldg(&ea[(size_t)e * F_EDGE + f]);
        float4 v = *reinterpret_cast<const float4*>(base + f * D_NN);
        acc.x += a * v.x; acc.y += a * v.y; acc.z += a * v.z; acc.w += a * v.w;
    }
    { // bias row, ea == 1
        float4 v = *reinterpret_cast<const float4*>(base + F_EDGE * D_NN);
        acc.x += v.x; acc.y += v.y; acc.z += v.z; acc.w += v.w;
    }
    red_add_v4(&g_agg[dst * D_NN + og * 4], acc);
}

// ---------------- K3: node-local: h = relu(agg + x@Wroot + bconv); hp = h@Wgat; scores ----------------
__global__ void k_node1(const float* __restrict__ x, const float* __restrict__ Wroot,
                        const float* __restrict__ bconv, const float* __restrict__ Wgat,
                        const float* __restrict__ a_src, const float* __restrict__ a_dst) {
    int n = blockIdx.x * blockDim.x + threadIdx.x;
    if (n >= N_NODES) return;
    float xv[D_IN], h[D_NN];
#pragma unroll
    for (int i = 0; i < D_IN; i++) xv[i] = __ldg(&x[n * D_IN + i]);
#pragma unroll
    for (int o = 0; o < D_NN; o++) {
        float a = g_agg[n * D_NN + o] + __ldg(&bconv[o]);
#pragma unroll
        for (int i = 0; i < D_IN; i++) a += xv[i] * __ldg(&Wroot[i * D_NN + o]);
        h[o] = fmaxf(a, 0.f);
    }
    float ss = 0.f, sd = 0.f;
#pragma unroll 4
    for (int o = 0; o < D_GAT; o++) {
        float v = 0.f;
#pragma unroll
        for (int i = 0; i < D_NN; i++) v += h[i] * __ldg(&Wgat[i * D_GAT + o]);
        g_hp[(size_t)n * D_GAT + o] = v;
        ss += v * __ldg(&a_src[o]);
        sd += v * __ldg(&a_dst[o]);
    }
    g_scs[n] = ss;
    g_scd[n] = sd;
    float es = lrelu(ss + sd);
    g_eself[n] = es;
    g_menc[n] = fenc(es);   // self-loop seeds the segment max (no race: edges run next kernel)
}

// ---------------- K4: edge pass A — leaky scores + segment max (ordered-uint atomicMax) ----------------
__global__ void k_edgeA(const int* __restrict__ ei) {
    int e = blockIdx.x * blockDim.x + threadIdx.x;
    if (e >= N_EDGES) return;
    int s = ei[e], d = ei[N_EDGES + e];
    float ev = lrelu(g_scs[s] + g_scd[d]);
    g_eedge[e] = ev;
    atomicMax(&g_menc[d], fenc(ev));
}

// ---------------- K5: node — decode max, self-loop exp seeds denom ----------------
__global__ void k_node2() {
    int n = blockIdx.x * blockDim.x + threadIdx.x;
    if (n >= N_NODES) return;
    float m = fdec(g_menc[n]);
    g_mf[n] = m;
    float ex = expf(g_eself[n] - m);
    g_exself[n] = ex;
    g_denom[n] = ex;
}

// ---------------- K6: edge pass B — exp + denom ----------------
__global__ void k_edgeB(const int* __restrict__ ei) {
    int e = blockIdx.x * blockDim.x + threadIdx.x;
    if (e >= N_EDGES) return;
    int d = ei[N_EDGES + e];
    float ex = expf(g_eedge[e] - g_mf[d]);
    g_exedge[e] = ex;
    atomicAdd(&g_denom[d], ex);
}

// ---------------- K7: node — init gat with self-loop contribution ----------------
__global__ void k_node3() {
    int t = blockIdx.x * blockDim.x + threadIdx.x;
    if (t >= N_NODES * (D_GAT / 4)) return;
    int n = t / (D_GAT / 4), og = t % (D_GAT / 4);
    float coeff = g_exself[n] / g_denom[n];
    float4 v = *reinterpret_cast<const float4*>(&g_hp[(size_t)n * D_GAT + og * 4]);
    v.x *= coeff; v.y *= coeff; v.z *= coeff; v.w *= coeff;
    *reinterpret_cast<float4*>(&g_gat[(size_t)n * D_GAT + og * 4]) = v;
}

// ---------------- K8: edge pass C — alpha * hp[src] scatter.  16 threads / edge ----------------
__global__ void k_edgeC(const int* __restrict__ ei) {
    int t = blockIdx.x * blockDim.x + threadIdx.x;
    if (t >= N_EDGES * (D_GAT / 4)) return;
    int e = t / (D_GAT / 4), og = t % (D_GAT / 4);
    int s = ei[e], d = ei[N_EDGES + e];
    float coeff = g_exedge[e] / g_denom[d];
    float4 v = *reinterpret_cast<const float4*>(&g_hp[(size_t)s * D_GAT + og * 4]);
    v.x *= coeff; v.y *= coeff; v.z *= coeff; v.w *= coeff;
    red_add_v4(&g_gat[(size_t)d * D_GAT + og * 4], v);
}

// ---------------- K9: relu(gat + bgat) + mean-pool scatter ----------------
__global__ void k_pool(const int* __restrict__ bids, const float* __restrict__ bgat) {
    int t = blockIdx.x * blockDim.x + threadIdx.x;
    if (t >= N_NODES * (D_GAT / 4)) return;
    int n = t / (D_GAT / 4), og = t % (D_GAT / 4);
    int g = bids[n];
    float4 v = *reinterpret_cast<const float4*>(&g_gat[(size_t)n * D_GAT + og * 4]);
    float4 b = *reinterpret_cast<const float4*>(&bgat[og * 4]);
    v.x = fmaxf(v.x + b.x, 0.f); v.y = fmaxf(v.y + b.y, 0.f);
    v.z = fmaxf(v.z + b.z, 0.f); v.w = fmaxf(v.w + b.w, 0.f);
    red_add_v4(&g_pooled[g * D_GAT + og * 4], v);
    if (og == 0) atomicAdd(&g_cnt[g], 1.f);
}

// ---------------- K10: MLP head, one block per graph ----------------
__global__ void k_head(const float* __restrict__ Wfc1, const float* __restrict__ bfc1,
                       const float* __restrict__ Wfc2, const float* __restrict__ bfc2,
                       float* __restrict__ out) {
    int g = blockIdx.x;
    int h = threadIdx.x;
    __shared__ float sp[D_GAT];
    __shared__ float red[HID];
    if (h < D_GAT) {
        float c = fmaxf(g_cnt[g], 1.f);
        sp[h] = g_pooled[g * D_GAT + h] / c;
    }
    __syncthreads();
    float acc = __ldg(&bfc1[h]);
#pragma unroll 8
    for (int k = 0; k < D_GAT; k++) acc += sp[k] * __ldg(&Wfc1[k * HID + h]);
    acc = fmaxf(acc, 0.f);
    red[h] = acc * __ldg(&Wfc2[h]);
    __syncthreads();
    for (int s = HID / 2; s > 0; s >>= 1) {
        if (h < s) red[h] += red[h + s];
        __syncthreads();
    }
    if (h == 0) out[g] = red[0] + __ldg(&bfc2[0]);
}

// ---------------- launch ----------------
extern "C" void kernel_launch(void* const* d_in, const int* in_sizes, int n_in,
                              void* d_out, int out_size) {
    const float* x     = (const float*)d_in[0];
    const int*   ei    = (const int*)d_in[1];     // int32 (JAX x64 disabled)
    const float* ea    = (const float*)d_in[2];
    const int*   bids  = (const int*)d_in[3];     // int32
    const float* We    = (const float*)d_in[4];
    const float* be    = (const float*)d_in[5];
    const float* Wroot = (const float*)d_in[6];
    const float* bconv = (const float*)d_in[7];
    const float* Wgat  = (const float*)d_in[8];
    const float* a_src = (const float*)d_in[9];
    const float* a_dst = (const float*)d_in[10];
    const float* bgat  = (const float*)d_in[11];
    const float* Wfc1  = (const float*)d_in[12];
    const float* bfc1  = (const float*)d_in[13];
    const float* Wfc2  = (const float*)d_in[14];
    const float* bfc2  = (const float*)d_in[15];
    float* out = (float*)d_out;

    k_init<<<256, 256>>>();
    k_x2<<<(N_NODES * X2_ROWS + 255) / 256, 256>>>(x, We, be);
    k_nnconv<<<(N_EDGES * 4 + 255) / 256, 256>>>(ei, ea);
    k_node1<<<(N_NODES + 127) / 128, 128>>>(x, Wroot, bconv, Wgat, a_src, a_dst);
    k_edgeA<<<(N_EDGES + 255) / 256, 256>>>(ei);
    k_node2<<<(N_NODES + 255) / 256, 256>>>();
    k_edgeB<<<(N_EDGES + 255) / 256, 256>>>(ei);
    k_node3<<<(N_NODES * (D_GAT / 4) + 255) / 256, 256>>>();
    k_edgeC<<<(N_EDGES * (D_GAT / 4) + 255) / 256, 256>>>(ei);
    k_pool<<<(N_NODES * (D_GAT / 4) + 255) / 256, 256>>>(bids, bgat);
    k_head<<<N_GRAPHS, HID>>>(Wfc1, bfc1, Wfc2, bfc2, out);
}

// round 3
// speedup vs baseline: 1.0450x; 1.0450x over previous
#include <cuda_runtime.h>

#define N_NODES  20000
#define N_EDGES  320000
#define F_EDGE   32
#define D_IN     16
#define D_NN     16
#define D_GAT    64
#define HID      128
#define N_GRAPHS 64
#define NEG_SLOPE 0.2f
#define X2_ROWS  33            // 32 edge-feature rows + 1 bias row (ea == 1)
#define X2_STRIDE (X2_ROWS * D_NN)   // 528 floats per node

// ---------------- scratch ----------------
static __device__ __align__(16) float g_X2[N_NODES * X2_STRIDE];   // 42.2 MB
static __device__ __align__(16) float g_agg[N_NODES * D_NN];
static __device__ __align__(16) float g_hp[N_NODES * D_GAT];
static __device__ __align__(16) float g_pooled[N_GRAPHS * D_GAT];
static __device__ float g_scs[N_NODES];
static __device__ float g_scd[N_NODES];
static __device__ float g_eself[N_NODES];
static __device__ float g_selfw[N_NODES];
static __device__ float g_invden[N_NODES];
static __device__ float g_cnt[N_GRAPHS];
// sorting scratch
static __device__ int g_hist_src[N_NODES], g_hist_dst[N_NODES];
static __device__ int g_rp_src[N_NODES + 1], g_rp_dst[N_NODES + 1];
static __device__ int g_cur_src[N_NODES], g_cur_dst[N_NODES];
static __device__ int g_se_e[N_EDGES], g_se_s[N_EDGES], g_se_d[N_EDGES]; // by-src order
static __device__ int g_de_s[N_EDGES];                                   // by-dst order: src ids
static __device__ float g_ev[N_EDGES];                                   // by-dst order: score -> exp

// ---------------- helpers ----------------
__device__ __forceinline__ void red_add_v4(float* p, float4 v) {
    asm volatile("red.global.add.v4.f32 [%0], {%1,%2,%3,%4};"
                 :: "l"(p), "f"(v.x), "f"(v.y), "f"(v.z), "f"(v.w) : "memory");
}
__device__ __forceinline__ float lrelu(float v) { return v > 0.f ? v : NEG_SLOPE * v; }

// ---------------- K0: zero accumulators + histograms ----------------
__global__ void k_init() {
    int t = blockIdx.x * blockDim.x + threadIdx.x;
    int stride = gridDim.x * blockDim.x;
    for (int i = t; i < N_NODES * D_NN; i += stride) g_agg[i] = 0.f;
    for (int i = t; i < N_NODES; i += stride) { g_hist_src[i] = 0; g_hist_dst[i] = 0; }
    for (int i = t; i < N_GRAPHS * D_GAT; i += stride) g_pooled[i] = 0.f;
    for (int i = t; i < N_GRAPHS; i += stride) g_cnt[i] = 0.f;
}

// ---------------- K1: degree histograms ----------------
__global__ void k_hist(const int* __restrict__ ei) {
    int e = blockIdx.x * blockDim.x + threadIdx.x;
    if (e >= N_EDGES) return;
    atomicAdd(&g_hist_src[ei[e]], 1);
    atomicAdd(&g_hist_dst[ei[N_EDGES + e]], 1);
}

// ---------------- K2: exclusive scan of both histograms (block 0 = src, block 1 = dst) ----------------
#define SCAN_CHUNK 20
__global__ void k_scan() {
    const int* hist = (blockIdx.x == 0) ? g_hist_src : g_hist_dst;
    int* rp  = (blockIdx.x == 0) ? g_rp_src  : g_rp_dst;
    int* cur = (blockIdx.x == 0) ? g_cur_src : g_cur_dst;
    __shared__ int part[1024];
    int tid = threadIdx.x;
    int base = tid * SCAN_CHUNK;
    int local[SCAN_CHUNK];
    int s = 0;
#pragma unroll
    for (int k = 0; k < SCAN_CHUNK; k++) {
        int idx = base + k;
        int v = (idx < N_NODES) ? hist[idx] : 0;
        local[k] = s; s += v;
    }
    part[tid] = s;
    __syncthreads();
    for (int off = 1; off < 1024; off <<= 1) {
        int v = 0;
        if (tid >= off) v = part[tid - off];
        __syncthreads();
        if (tid >= off) part[tid] += v;
        __syncthreads();
    }
    int offset = (tid > 0) ? part[tid - 1] : 0;
#pragma unroll
    for (int k = 0; k < SCAN_CHUNK; k++) {
        int idx = base + k;
        if (idx < N_NODES) { rp[idx] = offset + local[k]; cur[idx] = offset + local[k]; }
    }
    if (tid == 1023) rp[N_NODES] = part[1023];
}

// ---------------- K3: scatter into both sorted orders ----------------
__global__ void k_scatter(const int* __restrict__ ei) {
    int e = blockIdx.x * blockDim.x + threadIdx.x;
    if (e >= N_EDGES) return;
    int s = ei[e], d = ei[N_EDGES + e];
    int p = atomicAdd(&g_cur_src[s], 1);
    g_se_e[p] = e; g_se_s[p] = s; g_se_d[p] = d;
    int q = atomicAdd(&g_cur_dst[d], 1);
    g_de_s[q] = s;
}

// ---------------- K4: X2[n,f,o] = sum_i x[n,i] * We[f, i*16+o]  (f==32 -> be row) ----------------
__global__ void k_x2(const float* __restrict__ x, const float* __restrict__ We,
                     const float* __restrict__ be) {
    int t = blockIdx.x * blockDim.x + threadIdx.x;
    if (t >= N_NODES * X2_ROWS) return;
    int n = t / X2_ROWS, f = t % X2_ROWS;
    float xv[D_IN];
#pragma unroll
    for (int i = 0; i < D_IN; i++) xv[i] = __ldg(&x[n * D_IN + i]);
    const float* w = (f < F_EDGE) ? (We + (size_t)f * (D_IN * D_NN)) : be;
    float* out = g_X2 + (size_t)n * X2_STRIDE + f * D_NN;
#pragma unroll
    for (int o = 0; o < D_NN; o += 4) {
        float4 acc = make_float4(0.f, 0.f, 0.f, 0.f);
#pragma unroll
        for (int i = 0; i < D_IN; i++) {
            float4 wv = *reinterpret_cast<const float4*>(&w[i * D_NN + o]);
            acc.x += xv[i] * wv.x; acc.y += xv[i] * wv.y;
            acc.z += xv[i] * wv.z; acc.w += xv[i] * wv.w;
        }
        *reinterpret_cast<float4*>(&out[o]) = acc;
    }
}

// ---------------- K5: NNConv messages over src-sorted edges (4 threads/edge, X2 row L1-resident) ----------------
__global__ void k_nnconv(const float* __restrict__ ea) {
    int t = blockIdx.x * blockDim.x + threadIdx.x;
    if (t >= N_EDGES * 4) return;
    int idx = t >> 2, og = t & 3;
    int e = g_se_e[idx];
    int s = g_se_s[idx];
    int d = g_se_d[idx];
    const float* base = g_X2 + (size_t)s * X2_STRIDE + og * 4;
    // bias row (ea == 1)
    float4 acc = *reinterpret_cast<const float4*>(base + F_EDGE * D_NN);
#pragma unroll 8
    for (int f = 0; f < F_EDGE; f++) {
        float a = __ldg(&ea[(size_t)e * F_EDGE + f]);
        float4 v = *reinterpret_cast<const float4*>(base + f * D_NN);
        acc.x += a * v.x; acc.y += a * v.y; acc.z += a * v.z; acc.w += a * v.w;
    }
    red_add_v4(&g_agg[d * D_NN + og * 4], acc);
}

// ---------------- K6: cooperative node transform (16 threads/node) ----------------
// h = relu(agg + x@Wroot + bconv); hp = h@Wgat; scs/scd/eself
__global__ void k_node1(const float* __restrict__ x, const float* __restrict__ Wroot,
                        const float* __restrict__ bconv, const float* __restrict__ Wgat,
                        const float* __restrict__ a_src, const float* __restrict__ a_dst) {
    int tid = threadIdx.x;
    int n = blockIdx.x * 8 + (tid >> 4);   // grid sized so n < N_NODES always
    int j = tid & 15;
    __shared__ float sh[128];

    float xj = __ldg(&x[n * D_IN + j]);
    float a = g_agg[n * D_NN + j] + __ldg(&bconv[j]);
#pragma unroll
    for (int i = 0; i < D_IN; i++)
        a += __shfl_sync(0xffffffffu, xj, i, 16) * __ldg(&Wroot[i * D_NN + j]);
    float hj = fmaxf(a, 0.f);
    sh[tid] = hj;
    __syncwarp();
    const float* shh = &sh[tid & ~15];

    float4 hp4 = make_float4(0.f, 0.f, 0.f, 0.f);
#pragma unroll
    for (int i = 0; i < D_NN; i++) {
        float hv = shh[i];
        float4 wg = *reinterpret_cast<const float4*>(&Wgat[i * D_GAT + j * 4]);
        hp4.x += hv * wg.x; hp4.y += hv * wg.y; hp4.z += hv * wg.z; hp4.w += hv * wg.w;
    }
    *reinterpret_cast<float4*>(&g_hp[(size_t)n * D_GAT + j * 4]) = hp4;

    float4 as = *reinterpret_cast<const float4*>(&a_src[j * 4]);
    float4 ad = *reinterpret_cast<const float4*>(&a_dst[j * 4]);
    float ss = hp4.x * as.x + hp4.y * as.y + hp4.z * as.z + hp4.w * as.w;
    float sd = hp4.x * ad.x + hp4.y * ad.y + hp4.z * ad.z + hp4.w * ad.w;
#pragma unroll
    for (int off = 8; off >= 1; off >>= 1) {
        ss += __shfl_xor_sync(0xffffffffu, ss, off, 16);
        sd += __shfl_xor_sync(0xffffffffu, sd, off, 16);
    }
    if (j == 0) {
        g_scs[n] = ss;
        g_scd[n] = sd;
        g_eself[n] = lrelu(ss + sd);
    }
}

// ---------------- K7: GAT softmax per dst node (warp/node, no atomics) ----------------
__global__ void k_softmax() {
    int n = blockIdx.x * 8 + (threadIdx.x >> 5);   // exact grid
    int lane = threadIdx.x & 31;
    int beg = g_rp_dst[n], end = g_rp_dst[n + 1];
    float scd_n = g_scd[n];
    float eself = g_eself[n];

    float m = eself;
    for (int j = beg + lane; j < end; j += 32) {
        float ev = lrelu(g_scs[g_de_s[j]] + scd_n);
        g_ev[j] = ev;
        m = fmaxf(m, ev);
    }
#pragma unroll
    for (int off = 16; off >= 1; off >>= 1)
        m = fmaxf(m, __shfl_xor_sync(0xffffffffu, m, off));

    float sum = 0.f;
    for (int j = beg + lane; j < end; j += 32) {
        float ex = __expf(g_ev[j] - m);
        g_ev[j] = ex;
        sum += ex;
    }
    float exs = __expf(eself - m);
    if (lane == 0) sum += exs;
#pragma unroll
    for (int off = 16; off >= 1; off >>= 1)
        sum += __shfl_xor_sync(0xffffffffu, sum, off);
    if (lane == 0) {
        g_selfw[n] = exs;
        g_invden[n] = 1.f / sum;
    }
}

// ---------------- K8: GAT aggregate + bias/relu + mean-pool scatter (16 threads/node) ----------------
__global__ void k_gatagg(const int* __restrict__ bids, const float* __restrict__ bgat) {
    int tid = threadIdx.x;
    int n = blockIdx.x * 16 + (tid >> 4);   // exact grid
    int og = tid & 15;
    float inv = g_invden[n];
    float w0 = g_selfw[n] * inv;
    float4 acc = *reinterpret_cast<const float4*>(&g_hp[(size_t)n * D_GAT + og * 4]);
    acc.x *= w0; acc.y *= w0; acc.z *= w0; acc.w *= w0;
    int beg = g_rp_dst[n], end = g_rp_dst[n + 1];
    for (int j = beg; j < end; j++) {
        int s = g_de_s[j];
        float w = g_ev[j] * inv;
        float4 v = *reinterpret_cast<const float4*>(&g_hp[(size_t)s * D_GAT + og * 4]);
        acc.x += w * v.x; acc.y += w * v.y; acc.z += w * v.z; acc.w += w * v.w;
    }
    float4 b = *reinterpret_cast<const float4*>(&bgat[og * 4]);
    acc.x = fmaxf(acc.x + b.x, 0.f); acc.y = fmaxf(acc.y + b.y, 0.f);
    acc.z = fmaxf(acc.z + b.z, 0.f); acc.w = fmaxf(acc.w + b.w, 0.f);
    int g = bids[n];
    red_add_v4(&g_pooled[g * D_GAT + og * 4], acc);
    if (og == 0) atomicAdd(&g_cnt[g], 1.f);
}

// ---------------- K9: MLP head, one block per graph ----------------
__global__ void k_head(const float* __restrict__ Wfc1, const float* __restrict__ bfc1,
                       const float* __restrict__ Wfc2, const float* __restrict__ bfc2,
                       float* __restrict__ out) {
    int g = blockIdx.x;
    int h = threadIdx.x;
    __shared__ float sp[D_GAT];
    __shared__ float red[HID];
    if (h < D_GAT) {
        float c = fmaxf(g_cnt[g], 1.f);
        sp[h] = g_pooled[g * D_GAT + h] / c;
    }
    __syncthreads();
    float acc = __ldg(&bfc1[h]);
#pragma unroll 8
    for (int k = 0; k < D_GAT; k++) acc += sp[k] * __ldg(&Wfc1[k * HID + h]);
    acc = fmaxf(acc, 0.f);
    red[h] = acc * __ldg(&Wfc2[h]);
    __syncthreads();
    for (int s = HID / 2; s > 0; s >>= 1) {
        if (h < s) red[h] += red[h + s];
        __syncthreads();
    }
    if (h == 0) out[g] = red[0] + __ldg(&bfc2[0]);
}

// ---------------- launch ----------------
extern "C" void kernel_launch(void* const* d_in, const int* in_sizes, int n_in,
                              void* d_out, int out_size) {
    const float* x     = (const float*)d_in[0];
    const int*   ei    = (const int*)d_in[1];     // int32 (JAX x64 disabled)
    const float* ea    = (const float*)d_in[2];
    const int*   bids  = (const int*)d_in[3];     // int32
    const float* We    = (const float*)d_in[4];
    const float* be    = (const float*)d_in[5];
    const float* Wroot = (const float*)d_in[6];
    const float* bconv = (const float*)d_in[7];
    const float* Wgat  = (const float*)d_in[8];
    const float* a_src = (const float*)d_in[9];
    const float* a_dst = (const float*)d_in[10];
    const float* bgat  = (const float*)d_in[11];
    const float* Wfc1  = (const float*)d_in[12];
    const float* bfc1  = (const float*)d_in[13];
    const float* Wfc2  = (const float*)d_in[14];
    const float* bfc2  = (const float*)d_in[15];
    float* out = (float*)d_out;

    k_init<<<256, 256>>>();
    k_hist<<<(N_EDGES + 255) / 256, 256>>>(ei);
    k_scan<<<2, 1024>>>();
    k_scatter<<<(N_EDGES + 255) / 256, 256>>>(ei);
    k_x2<<<(N_NODES * X2_ROWS + 255) / 256, 256>>>(x, We, be);
    k_nnconv<<<(N_EDGES * 4 + 255) / 256, 256>>>(ea);
    k_node1<<<N_NODES / 8, 128>>>(x, Wroot, bconv, Wgat, a_src, a_dst);
    k_softmax<<<N_NODES / 8, 256>>>();
    k_gatagg<<<N_NODES / 16, 256>>>(bids, bgat);
    k_head<<<N_GRAPHS, HID>>>(Wfc1, bfc1, Wfc2, bfc2, out);
}

// round 4
// speedup vs baseline: 1.7780x; 1.7014x over previous
#include <cuda_runtime.h>

#define N_NODES  20000
#define N_EDGES  320000
#define F_EDGE   32
#define D_IN     16
#define D_NN     16
#define D_GAT    64
#define HID      128
#define N_GRAPHS 64
#define NEG_SLOPE 0.2f

// ---------------- scratch ----------------
static __device__ __align__(16) float g_WeT[F_EDGE * D_IN * D_NN];   // WeT[f][o][i]
static __device__ __align__(16) float g_agg[N_NODES * D_NN];
static __device__ __align__(16) float g_hp[N_NODES * D_GAT];
static __device__ __align__(16) float g_pooled[N_GRAPHS * D_GAT];
static __device__ float g_scs[N_NODES];
static __device__ float g_scd[N_NODES];
static __device__ float g_eself[N_NODES];
static __device__ float g_selfw[N_NODES];
static __device__ float g_invden[N_NODES];
static __device__ float g_cnt[N_GRAPHS];
// sorting scratch
static __device__ int g_hist_src[N_NODES], g_hist_dst[N_NODES];
static __device__ int g_rp_src[N_NODES + 1], g_rp_dst[N_NODES + 1];
static __device__ int g_cur_src[N_NODES], g_cur_dst[N_NODES];
static __device__ __align__(8) int2 g_se_ed[N_EDGES];  // by-src order: (edge id, dst)
static __device__ int g_de_s[N_EDGES];                 // by-dst order: src ids
static __device__ float g_ev[N_EDGES];                 // by-dst order: score -> exp

// ---------------- helpers ----------------
__device__ __forceinline__ void red_add_v4(float* p, float4 v) {
    asm volatile("red.global.add.v4.f32 [%0], {%1,%2,%3,%4};"
                 :: "l"(p), "f"(v.x), "f"(v.y), "f"(v.z), "f"(v.w) : "memory");
}
__device__ __forceinline__ void red_add_f32(float* p, float v) {
    asm volatile("red.global.add.f32 [%0], %1;" :: "l"(p), "f"(v) : "memory");
}
__device__ __forceinline__ float lrelu(float v) { return v > 0.f ? v : NEG_SLOPE * v; }

// ---------------- K0: zero accumulators + histograms + build WeT ----------------
__global__ void k_init(const float* __restrict__ We) {
    int t = blockIdx.x * blockDim.x + threadIdx.x;
    int stride = gridDim.x * blockDim.x;
    for (int i = t; i < N_NODES * D_NN; i += stride) g_agg[i] = 0.f;
    for (int i = t; i < N_NODES; i += stride) { g_hist_src[i] = 0; g_hist_dst[i] = 0; }
    for (int i = t; i < N_GRAPHS * D_GAT; i += stride) g_pooled[i] = 0.f;
    for (int i = t; i < N_GRAPHS; i += stride) g_cnt[i] = 0.f;
    for (int i = t; i < F_EDGE * D_IN * D_NN; i += stride) {
        int f = i >> 8, r = i & 255, o = r >> 4, ii = r & 15;
        g_WeT[(f << 8) + (o << 4) + ii] = We[(f << 8) + (ii << 4) + o];
    }
}

// ---------------- K1: degree histograms ----------------
__global__ void k_hist(const int* __restrict__ ei) {
    int e = blockIdx.x * blockDim.x + threadIdx.x;
    if (e >= N_EDGES) return;
    atomicAdd(&g_hist_src[ei[e]], 1);
    atomicAdd(&g_hist_dst[ei[N_EDGES + e]], 1);
}

// ---------------- K2: exclusive scan of both histograms (block 0 = src, block 1 = dst) ----------------
#define SCAN_CHUNK 20
__global__ void k_scan() {
    const int* hist = (blockIdx.x == 0) ? g_hist_src : g_hist_dst;
    int* rp  = (blockIdx.x == 0) ? g_rp_src  : g_rp_dst;
    int* cur = (blockIdx.x == 0) ? g_cur_src : g_cur_dst;
    __shared__ int part[1024];
    int tid = threadIdx.x;
    int base = tid * SCAN_CHUNK;
    int local[SCAN_CHUNK];
    int s = 0;
#pragma unroll
    for (int k = 0; k < SCAN_CHUNK; k++) {
        int idx = base + k;
        int v = (idx < N_NODES) ? hist[idx] : 0;
        local[k] = s; s += v;
    }
    part[tid] = s;
    __syncthreads();
    for (int off = 1; off < 1024; off <<= 1) {
        int v = 0;
        if (tid >= off) v = part[tid - off];
        __syncthreads();
        if (tid >= off) part[tid] += v;
        __syncthreads();
    }
    int offset = (tid > 0) ? part[tid - 1] : 0;
#pragma unroll
    for (int k = 0; k < SCAN_CHUNK; k++) {
        int idx = base + k;
        if (idx < N_NODES) { rp[idx] = offset + local[k]; cur[idx] = offset + local[k]; }
    }
    if (tid == 1023) rp[N_NODES] = part[1023];
}

// ---------------- K3: scatter into both sorted orders ----------------
__global__ void k_scatter(const int* __restrict__ ei) {
    int e = blockIdx.x * blockDim.x + threadIdx.x;
    if (e >= N_EDGES) return;
    int s = ei[e], d = ei[N_EDGES + e];
    int p = atomicAdd(&g_cur_src[s], 1);
    g_se_ed[p] = make_int2(e, d);
    int q = atomicAdd(&g_cur_dst[d], 1);
    g_de_s[q] = s;
}

// ---------------- K4: NNConv, warp per 2 src nodes, X2 register-resident ----------------
// lane l: group g = l>>4, o = l&15; X2 reg[k] = X2[16*g + k][o] (k = 0..15)
// X2[f][o] = sum_i x[src][i] * We[f][i*16+o] = sum_i x[i] * WeT[f][o][i]
// per edge: msg[o] = sum_f ea[f] * X2[f][o]; scatter red.add to g_agg[dst]
__global__ void k_nnconv(const float* __restrict__ x, const float* __restrict__ ea) {
    int w = (blockIdx.x * blockDim.x + threadIdx.x) >> 5;  // warp id < 10000
    int lane = threadIdx.x & 31;
    int g = lane >> 4, o = lane & 15;

    int n0 = 2 * w, n1 = 2 * w + 1;
    // x rows (broadcast loads, L1)
    float4 xa[4], xb[4];
#pragma unroll
    for (int c = 0; c < 4; c++) {
        xa[c] = *reinterpret_cast<const float4*>(&x[n0 * D_IN + c * 4]);
        xb[c] = *reinterpret_cast<const float4*>(&x[n1 * D_IN + c * 4]);
    }
    float X2a[16], X2b[16];
#pragma unroll
    for (int k = 0; k < 16; k++) {
        const float4* wt = reinterpret_cast<const float4*>(
            &g_WeT[((16 * g + k) << 8) + (o << 4)]);
        float sa = 0.f, sb = 0.f;
#pragma unroll
        for (int c = 0; c < 4; c++) {
            float4 wv = wt[c];
            sa += xa[c].x * wv.x + xa[c].y * wv.y + xa[c].z * wv.z + xa[c].w * wv.w;
            sb += xb[c].x * wv.x + xb[c].y * wv.y + xb[c].z * wv.z + xb[c].w * wv.w;
        }
        X2a[k] = sa; X2b[k] = sb;
    }

#pragma unroll
    for (int half = 0; half < 2; half++) {
        int n = half ? n1 : n0;
        const float* X2 = half ? X2b : X2a;
        int beg = g_rp_src[n], end = g_rp_src[n + 1];
        if (beg >= end) continue;
        int2 ed = g_se_ed[beg];
        float a0 = ea[(size_t)ed.x * F_EDGE + lane];
        for (int j = beg; j < end; j++) {
            int2 edn; float a1;
            if (j + 1 < end) {
                edn = g_se_ed[j + 1];
                a1 = ea[(size_t)edn.x * F_EDGE + lane];
            } else { edn = ed; a1 = 0.f; }
            float p = 0.f;
#pragma unroll
            for (int k = 0; k < 16; k++)
                p += __shfl_sync(0xffffffffu, a0, (lane & 16) + k) *
                     ((half == 0) ? X2a[k] : X2b[k]);
            p += __shfl_xor_sync(0xffffffffu, p, 16);
            if (lane < 16) red_add_f32(&g_agg[ed.y * D_NN + lane], p);
            ed = edn; a0 = a1;
        }
        (void)X2;
    }
}

// ---------------- K5: cooperative node transform (16 threads/node) ----------------
// h = relu(agg + x@(Wroot + beM) + bconv); hp = h@Wgat; scs/scd/eself
// (beM = reshape(be, [D_IN, D_NN]) is the NNConv edge-bias term folded in)
__global__ void k_node1(const float* __restrict__ x, const float* __restrict__ Wroot,
                        const float* __restrict__ be, const float* __restrict__ bconv,
                        const float* __restrict__ Wgat,
                        const float* __restrict__ a_src, const float* __restrict__ a_dst) {
    int tid = threadIdx.x;
    int n = blockIdx.x * 8 + (tid >> 4);   // exact grid
    int j = tid & 15;
    __shared__ float sh[128];

    float xj = __ldg(&x[n * D_IN + j]);
    float a = g_agg[n * D_NN + j] + __ldg(&bconv[j]);
#pragma unroll
    for (int i = 0; i < D_IN; i++)
        a += __shfl_sync(0xffffffffu, xj, i, 16) *
             (__ldg(&Wroot[i * D_NN + j]) + __ldg(&be[i * D_NN + j]));
    float hj = fmaxf(a, 0.f);
    sh[tid] = hj;
    __syncwarp();
    const float* shh = &sh[tid & ~15];

    float4 hp4 = make_float4(0.f, 0.f, 0.f, 0.f);
#pragma unroll
    for (int i = 0; i < D_NN; i++) {
        float hv = shh[i];
        float4 wg = *reinterpret_cast<const float4*>(&Wgat[i * D_GAT + j * 4]);
        hp4.x += hv * wg.x; hp4.y += hv * wg.y; hp4.z += hv * wg.z; hp4.w += hv * wg.w;
    }
    *reinterpret_cast<float4*>(&g_hp[(size_t)n * D_GAT + j * 4]) = hp4;

    float4 as = *reinterpret_cast<const float4*>(&a_src[j * 4]);
    float4 ad = *reinterpret_cast<const float4*>(&a_dst[j * 4]);
    float ss = hp4.x * as.x + hp4.y * as.y + hp4.z * as.z + hp4.w * as.w;
    float sd = hp4.x * ad.x + hp4.y * ad.y + hp4.z * ad.z + hp4.w * ad.w;
#pragma unroll
    for (int off = 8; off >= 1; off >>= 1) {
        ss += __shfl_xor_sync(0xffffffffu, ss, off, 16);
        sd += __shfl_xor_sync(0xffffffffu, sd, off, 16);
    }
    if (j == 0) {
        g_scs[n] = ss;
        g_scd[n] = sd;
        g_eself[n] = lrelu(ss + sd);
    }
}

// ---------------- K6: GAT softmax per dst node (warp/node, no atomics) ----------------
__global__ void k_softmax() {
    int n = blockIdx.x * 8 + (threadIdx.x >> 5);   // exact grid
    int lane = threadIdx.x & 31;
    int beg = g_rp_dst[n], end = g_rp_dst[n + 1];
    float scd_n = g_scd[n];
    float eself = g_eself[n];

    float m = eself;
    for (int j = beg + lane; j < end; j += 32) {
        float ev = lrelu(g_scs[g_de_s[j]] + scd_n);
        g_ev[j] = ev;
        m = fmaxf(m, ev);
    }
#pragma unroll
    for (int off = 16; off >= 1; off >>= 1)
        m = fmaxf(m, __shfl_xor_sync(0xffffffffu, m, off));

    float sum = 0.f;
    for (int j = beg + lane; j < end; j += 32) {
        float ex = __expf(g_ev[j] - m);
        g_ev[j] = ex;
        sum += ex;
    }
    float exs = __expf(eself - m);
    if (lane == 0) sum += exs;
#pragma unroll
    for (int off = 16; off >= 1; off >>= 1)
        sum += __shfl_xor_sync(0xffffffffu, sum, off);
    if (lane == 0) {
        g_selfw[n] = exs;
        g_invden[n] = 1.f / sum;
    }
}

// ---------------- K7: GAT aggregate + bias/relu + mean-pool scatter (16 threads/node) ----------------
__global__ void k_gatagg(const int* __restrict__ bids, const float* __restrict__ bgat) {
    int tid = threadIdx.x;
    int n = blockIdx.x * 16 + (tid >> 4);   // exact grid
    int og = tid & 15;
    float inv = g_invden[n];
    float w0 = g_selfw[n] * inv;
    float4 acc = *reinterpret_cast<const float4*>(&g_hp[(size_t)n * D_GAT + og * 4]);
    acc.x *= w0; acc.y *= w0; acc.z *= w0; acc.w *= w0;
    int beg = g_rp_dst[n], end = g_rp_dst[n + 1];
    for (int j = beg; j < end; j++) {
        int s = g_de_s[j];
        float w = g_ev[j] * inv;
        float4 v = *reinterpret_cast<const float4*>(&g_hp[(size_t)s * D_GAT + og * 4]);
        acc.x += w * v.x; acc.y += w * v.y; acc.z += w * v.z; acc.w += w * v.w;
    }
    float4 b = *reinterpret_cast<const float4*>(&bgat[og * 4]);
    acc.x = fmaxf(acc.x + b.x, 0.f); acc.y = fmaxf(acc.y + b.y, 0.f);
    acc.z = fmaxf(acc.z + b.z, 0.f); acc.w = fmaxf(acc.w + b.w, 0.f);
    int g = bids[n];
    red_add_v4(&g_pooled[g * D_GAT + og * 4], acc);
    if (og == 0) atomicAdd(&g_cnt[g], 1.f);
}

// ---------------- K8: MLP head, one block per graph ----------------
__global__ void k_head(const float* __restrict__ Wfc1, const float* __restrict__ bfc1,
                       const float* __restrict__ Wfc2, const float* __restrict__ bfc2,
                       float* __restrict__ out) {
    int g = blockIdx.x;
    int h = threadIdx.x;
    __shared__ float sp[D_GAT];
    __shared__ float red[HID];
    if (h < D_GAT) {
        float c = fmaxf(g_cnt[g], 1.f);
        sp[h] = g_pooled[g * D_GAT + h] / c;
    }
    __syncthreads();
    float acc = __ldg(&bfc1[h]);
#pragma unroll 8
    for (int k = 0; k < D_GAT; k++) acc += sp[k] * __ldg(&Wfc1[k * HID + h]);
    acc = fmaxf(acc, 0.f);
    red[h] = acc * __ldg(&Wfc2[h]);
    __syncthreads();
    for (int s = HID / 2; s > 0; s >>= 1) {
        if (h < s) red[h] += red[h + s];
        __syncthreads();
    }
    if (h == 0) out[g] = red[0] + __ldg(&bfc2[0]);
}

// ---------------- launch ----------------
extern "C" void kernel_launch(void* const* d_in, const int* in_sizes, int n_in,
                              void* d_out, int out_size) {
    const float* x     = (const float*)d_in[0];
    const int*   ei    = (const int*)d_in[1];     // int32 (JAX x64 disabled)
    const float* ea    = (const float*)d_in[2];
    const int*   bids  = (const int*)d_in[3];     // int32
    const float* We    = (const float*)d_in[4];
    const float* be    = (const float*)d_in[5];
    const float* Wroot = (const float*)d_in[6];
    const float* bconv = (const float*)d_in[7];
    const float* Wgat  = (const float*)d_in[8];
    const float* a_src = (const float*)d_in[9];
    const float* a_dst = (const float*)d_in[10];
    const float* bgat  = (const float*)d_in[11];
    const float* Wfc1  = (const float*)d_in[12];
    const float* bfc1  = (const float*)d_in[13];
    const float* Wfc2  = (const float*)d_in[14];
    const float* bfc2  = (const float*)d_in[15];
    float* out = (float*)d_out;

    k_init<<<256, 256>>>(We);
    k_hist<<<(N_EDGES + 255) / 256, 256>>>(ei);
    k_scan<<<2, 1024>>>();
    k_scatter<<<(N_EDGES + 255) / 256, 256>>>(ei);
    k_nnconv<<<(N_NODES / 2 * 32 + 255) / 256, 256>>>(x, ea);
    k_node1<<<N_NODES / 8, 128>>>(x, Wroot, be, bconv, Wgat, a_src, a_dst);
    k_softmax<<<N_NODES / 8, 256>>>();
    k_gatagg<<<N_NODES / 16, 256>>>(bids, bgat);
    k_head<<<N_GRAPHS, HID>>>(Wfc1, bfc1, Wfc2, bfc2, out);
}